// round 12
// baseline (speedup 1.0000x reference)
#include <cuda_runtime.h>
#include <cuda_fp16.h>
#include <cstdint>
#include <math.h>

#define B_ 8
#define S_ 2048
#define H_ 256
#define BSROWS (B_*S_)

// ----------------------------- scratch ------------------------------------
__device__ __half g_xh[(size_t)BSROWS * H_];
__device__ __half g_qh[(size_t)BSROWS * H_];
__device__ __half g_kh[(size_t)BSROWS * H_];
__device__ __half g_vh[(size_t)BSROWS * H_];
__device__ __half g_wh[3 * H_ * H_];
__device__ float2 g_cs[S_ * (H_ / 2)];
// split-K partials: 128 split q-tiles x 2 chunks x (64x256 O + 64 li)
__device__ float g_pO[256 * 64 * 256];
__device__ float g_pLi[256 * 64];

// ----------------------------- PTX helpers --------------------------------
__device__ __forceinline__ uint32_t smem_u32(const void* p) {
    uint32_t a;
    asm("{ .reg .u64 t; cvta.to.shared.u64 t, %1; cvt.u32.u64 %0, t; }" : "=r"(a) : "l"(p));
    return a;
}
#define CP16(dst, src) asm volatile("cp.async.cg.shared.global [%0], [%1], 16;" :: "r"(dst), "l"(src))
#define CP_COMMIT()    asm volatile("cp.async.commit_group;" ::: "memory")
#define CP_WAIT(n)     asm volatile("cp.async.wait_group %0;" :: "n"(n) : "memory")
#define PAIR_BAR(id)   asm volatile("bar.sync %0, 64;" :: "r"((id) + 1) : "memory")

__device__ __forceinline__ void ldm_x4(uint32_t& r0, uint32_t& r1, uint32_t& r2,
                                       uint32_t& r3, uint32_t addr) {
    asm volatile("ldmatrix.sync.aligned.m8n8.x4.shared.b16 {%0,%1,%2,%3}, [%4];"
                 : "=r"(r0), "=r"(r1), "=r"(r2), "=r"(r3) : "r"(addr));
}
__device__ __forceinline__ void ldm_x4t(uint32_t& r0, uint32_t& r1, uint32_t& r2,
                                        uint32_t& r3, uint32_t addr) {
    asm volatile("ldmatrix.sync.aligned.m8n8.x4.trans.shared.b16 {%0,%1,%2,%3}, [%4];"
                 : "=r"(r0), "=r"(r1), "=r"(r2), "=r"(r3) : "r"(addr));
}
__device__ __forceinline__ void hmma(float* c, uint32_t a0, uint32_t a1, uint32_t a2,
                                     uint32_t a3, uint32_t b0, uint32_t b1) {
    asm volatile(
        "mma.sync.aligned.m16n8k16.row.col.f32.f16.f16.f32 "
        "{%0,%1,%2,%3}, {%4,%5,%6,%7}, {%8,%9}, {%0,%1,%2,%3};"
        : "+f"(c[0]), "+f"(c[1]), "+f"(c[2]), "+f"(c[3])
        : "r"(a0), "r"(a1), "r"(a2), "r"(a3), "r"(b0), "r"(b1));
}

// ----------------------------- prep (fused) --------------------------------
__global__ __launch_bounds__(256) void prep_kernel(
    const float* __restrict__ x, const float* __restrict__ wq,
    const float* __restrict__ wk, const float* __restrict__ wv)
{
    const int bid = blockIdx.x, tid = threadIdx.x;
    if (bid < 128) {
        int i = tid & 127;
        double e = -2.0 * ((double)i - 1.0) / 256.0;
        float theta = (float)exp(e * 9.210340371976184);   // ln(10000)
        int p0 = bid * 16 + (tid >> 7) * 8;
        #pragma unroll
        for (int p = 0; p < 8; p++) {
            int pos = p0 + p;
            float ang = __fmul_rn((float)pos, theta);
            float sv, cv;
            sincosf(ang, &sv, &cv);
            g_cs[pos * 128 + i] = make_float2(cv, sv);
        }
    } else if (bid < 320) {
        int zi = bid - 128;
        int z = zi >> 6;
        int i = (zi & 63) * 256 + tid;
        const float* w = (z == 0) ? wq : (z == 1) ? wk : wv;
        float4 v = ((const float4*)w)[i];
        __half2* dst = (__half2*)(g_wh + (size_t)z * H_ * H_);
        dst[2 * i]     = __floats2half2_rn(v.x, v.y);
        dst[2 * i + 1] = __floats2half2_rn(v.z, v.w);
    } else {
        int i = (bid - 320) * 256 + tid;
        float4 v = ((const float4*)x)[i];
        ((__half2*)g_xh)[2 * i]     = __floats2half2_rn(v.x, v.y);
        ((__half2*)g_xh)[2 * i + 1] = __floats2half2_rn(v.z, v.w);
    }
}

// ----------------------------- proj (HMMA) ---------------------------------
// A-resident z-loop: CTA tile 256(M) x 128(N), K=256; one wave of 128 CTAs.
#define PRJ_SMEM 196608
__global__ __launch_bounds__(512, 1) void proj_kernel() {
    extern __shared__ char sm[];
    uint32_t sb = smem_u32(sm);
    const int tid = threadIdx.x, lane = tid & 31, w = tid >> 5;
    const int wm = w >> 1, wn = w & 1;
    const int m0 = blockIdx.x * 256, n0g = blockIdx.y * 128;
    const uint32_t BOFF = 131072;

    for (int i = tid; i < 8192; i += 512) {
        int row = i >> 5, g = i & 31;
        uint32_t sw = row * 512 + ((g ^ (row & 7)) << 4);
        CP16(sb + sw, g_xh + (((size_t)(m0 + row)) << 8) + g * 8);
    }
    for (int i = tid; i < 4096; i += 512) {
        int row = i >> 5, g = i & 31;
        uint32_t sw = row * 512 + ((g ^ (row & 7)) << 4);
        CP16(sb + BOFF + sw, g_wh + (((size_t)(n0g + row)) << 8) + g * 8);
    }
    CP_COMMIT();
    CP_WAIT(0);
    __syncthreads();

    #pragma unroll 1
    for (int z = 0; z < 3; z++) {
        float O[2][8][4];
        #pragma unroll
        for (int mi = 0; mi < 2; mi++)
            #pragma unroll
            for (int j = 0; j < 8; j++)
                #pragma unroll
                for (int c = 0; c < 4; c++) O[mi][j][c] = 0.f;

        #pragma unroll
        for (int ks = 0; ks < 16; ks++) {
            uint32_t A[2][4];
            #pragma unroll
            for (int mi = 0; mi < 2; mi++) {
                uint32_t aRow = wm * 32 + mi * 16 + (lane & 15);
                uint32_t g = ks * 2 + (lane >> 4);
                ldm_x4(A[mi][0], A[mi][1], A[mi][2], A[mi][3],
                       sb + aRow * 512 + ((g ^ (aRow & 7)) << 4));
            }
            #pragma unroll
            for (int nb = 0; nb < 4; nb++) {
                uint32_t nrow = wn * 64 + nb * 16 + (lane & 7) + ((lane >> 4) << 3);
                uint32_t g = ks * 2 + ((lane >> 3) & 1);
                uint32_t b0, b1, b2, b3;
                ldm_x4(b0, b1, b2, b3, sb + BOFF + nrow * 512 + ((g ^ (nrow & 7)) << 4));
                #pragma unroll
                for (int mi = 0; mi < 2; mi++) {
                    hmma(O[mi][2 * nb],     A[mi][0], A[mi][1], A[mi][2], A[mi][3], b0, b1);
                    hmma(O[mi][2 * nb + 1], A[mi][0], A[mi][1], A[mi][2], A[mi][3], b2, b3);
                }
            }
        }

        __syncthreads();
        if (z < 2) {
            const __half* wsrc = g_wh + (size_t)(z + 1) * H_ * H_;
            for (int i = tid; i < 4096; i += 512) {
                int row = i >> 5, g = i & 31;
                uint32_t sw = row * 512 + ((g ^ (row & 7)) << 4);
                CP16(sb + BOFF + sw, wsrc + (((size_t)(n0g + row)) << 8) + g * 8);
            }
            CP_COMMIT();
        }

        __half* outp = (z == 0) ? g_qh : (z == 1) ? g_kh : g_vh;
        #pragma unroll
        for (int mi = 0; mi < 2; mi++) {
            int r0 = m0 + wm * 32 + mi * 16 + (lane >> 2), r1 = r0 + 8;
            int pos0 = r0 & (S_ - 1), pos1 = r1 & (S_ - 1);
            #pragma unroll
            for (int j = 0; j < 8; j++) {
                int col = n0g + wn * 64 + j * 8 + (lane & 3) * 2;
                if (z < 2) {
                    float2 cs0 = g_cs[pos0 * 128 + (col >> 1)];
                    float2 cs1 = g_cs[pos1 * 128 + (col >> 1)];
                    *(__half2*)(outp + (((size_t)r0) << 8) + col) =
                        __floats2half2_rn(cs0.x * O[mi][j][0] + cs0.y * O[mi][j][1],
                                          -cs0.y * O[mi][j][0] + cs0.x * O[mi][j][1]);
                    *(__half2*)(outp + (((size_t)r1) << 8) + col) =
                        __floats2half2_rn(cs1.x * O[mi][j][2] + cs1.y * O[mi][j][3],
                                          -cs1.y * O[mi][j][2] + cs1.x * O[mi][j][3]);
                } else {
                    *(__half2*)(outp + (((size_t)r0) << 8) + col) =
                        __floats2half2_rn(O[mi][j][0], O[mi][j][1]);
                    *(__half2*)(outp + (((size_t)r1) << 8) + col) =
                        __floats2half2_rn(O[mi][j][2], O[mi][j][3]);
                }
            }
        }
        if (z < 2) {
            CP_WAIT(0);
            __syncthreads();
        }
    }
}

// ----------------------------- flash (HMMA, split-K, 2 CTA/SM) -------------
// One work unit per CTA: (batch, qt, key-chunk). qt>=16 split into 2 chunks
// writing unnormalized O + li partials; merge kernel combines. Single-buffer
// K/V (105.5KB smem) + <=128 regs -> 2 CTAs/SM; co-resident CTA fills pipe.
#define SQ_ 0
#define SK_ 32768
#define SV_ 65536
#define SP_ 98304
#define SLI_ 107520
#define FL_SMEM 108032
#define SCALE2 0.0901684400054f   /* log2(e)/16 */

__global__ __launch_bounds__(256, 2) void flash_kernel(float* __restrict__ out) {
    extern __shared__ char sm[];
    uint32_t sb = smem_u32(sm);
    float* liS = (float*)(sm + SLI_);
    const int tid = threadIdx.x, lane = tid & 31, w = tid >> 5;
    const int rg = w >> 1, ch = w & 1;

    // ---- work-unit decode (descending weight order) ----
    int qt, bb, kb, ke, chunk, split;
    {
        int bid = blockIdx.x;
        if (bid < 256) {                 // split tiles: qt 31..16, 2 chunks x 8 b
            qt = 31 - (bid >> 4);
            int r = bid & 15;
            bb = r >> 1; chunk = r & 1;
            int c0 = (qt + 2) >> 1;
            kb = chunk ? c0 : 0;
            ke = chunk ? (qt + 1) : c0;
            split = 1;
        } else {                         // singles: qt 15..0
            int i = bid - 256;
            qt = 15 - (i >> 3); bb = i & 7;
            kb = 0; ke = qt + 1; chunk = 0; split = 0;
        }
    }
    const int q0 = qt * 64;

    // Q tile (its completion folded into first iteration's wait)
    for (int i = tid; i < 2048; i += 256) {
        int row = i >> 5, g = i & 31;
        uint32_t sw = row * 512 + ((g ^ (row & 7)) << 4);
        CP16(sb + SQ_ + sw, g_qh + (((size_t)(bb * S_ + q0 + row)) << 8) + g * 8);
    }
    CP_COMMIT();

    float O[16][4];
    #pragma unroll
    for (int j = 0; j < 16; j++)
        #pragma unroll
        for (int c = 0; c < 4; c++) O[j][c] = 0.f;
    float li0 = 0.f, li1 = 0.f;

    const int aSel = lane >> 4;
    const uint32_t aRow = rg * 16 + (lane & 15);
    const uint32_t aQbase = sb + SQ_ + aRow * 512;
    const int aXor = aRow & 7;

    for (int kt = kb; kt < ke; kt++) {
        __syncthreads();                 // all PV reads of K/V done
        for (int i = tid; i < 2048; i += 256) {
            int row = i >> 5, g = i & 31;
            uint32_t sw = row * 512 + ((g ^ (row & 7)) << 4);
            size_t go = (((size_t)(bb * S_ + kt * 64 + row)) << 8) + g * 8;
            CP16(sb + SK_ + sw, g_kh + go);
            CP16(sb + SV_ + sw, g_vh + go);
        }
        CP_COMMIT();
        CP_WAIT(0);
        __syncthreads();

        // ---- QK^T (Q ldsm per iter; regs budgeted for 2 CTA/SM) ----
        float S4[4][4];
        #pragma unroll
        for (int j = 0; j < 4; j++)
            #pragma unroll
            for (int c = 0; c < 4; c++) S4[j][c] = 0.f;

        #pragma unroll
        for (int ks = 0; ks < 16; ks++) {
            uint32_t a0, a1, a2, a3;
            ldm_x4(a0, a1, a2, a3, aQbase + (((ks * 2 + aSel) ^ aXor) << 4));
            #pragma unroll
            for (int nblk = 0; nblk < 2; nblk++) {
                uint32_t nrow = ch * 32 + nblk * 16 + (lane & 7) + ((lane >> 4) << 3);
                uint32_t g = ks * 2 + ((lane >> 3) & 1);
                uint32_t b0, b1, b2, b3;
                ldm_x4(b0, b1, b2, b3, sb + SK_ + nrow * 512 + ((g ^ (nrow & 7)) << 4));
                hmma(S4[2 * nblk],     a0, a1, a2, a3, b0, b1);
                hmma(S4[2 * nblk + 1], a0, a1, a2, a3, b2, b3);
            }
        }

        // ---- softmax chunk ----
        {
            const int row0 = q0 + rg * 16 + (lane >> 2);
            const int colb = kt * 64 + ch * 32 + (lane & 3) * 2;
            const bool diag = (kt == qt);
            uint32_t pb = SP_ + (rg * 16 + (lane >> 2)) * 144 +
                          (ch * 32 + (lane & 3) * 2) * 2;
            #pragma unroll
            for (int cnk = 0; cnk < 4; cnk++) {
                int c0 = colb + cnk * 8;
                float p00 = exp2f(S4[cnk][0] * SCALE2);
                float p01 = exp2f(S4[cnk][1] * SCALE2);
                float p10 = exp2f(S4[cnk][2] * SCALE2);
                float p11 = exp2f(S4[cnk][3] * SCALE2);
                if (diag) {
                    if (c0     > row0) p00 = 0.f;
                    if (c0 + 1 > row0) p01 = 0.f;
                    if (c0     > row0 + 8) p10 = 0.f;
                    if (c0 + 1 > row0 + 8) p11 = 0.f;
                }
                li0 += p00 + p01;
                li1 += p10 + p11;
                *(__half2*)(sm + pb + cnk * 16)           = __floats2half2_rn(p00, p01);
                *(__half2*)(sm + pb + cnk * 16 + 8 * 144) = __floats2half2_rn(p10, p11);
            }
        }
        PAIR_BAR(rg);                    // P visible within the rg pair

        // ---- PV ----
        const uint32_t pBase = sb + SP_ + (rg * 16 + (lane & 15)) * 144;
        #pragma unroll
        for (int kc = 0; kc < 4; kc++) {
            uint32_t a0, a1, a2, a3;
            ldm_x4(a0, a1, a2, a3, pBase + ((kc * 2 + aSel) << 4));
            #pragma unroll
            for (int nb = 0; nb < 8; nb++) {
                uint32_t n0v = ch * 128 + nb * 16;
                uint32_t krow = kc * 16 + (lane & 7) + (((lane >> 3) & 1) << 3);
                uint32_t g = (n0v >> 3) + (lane >> 4);
                uint32_t b0, b1, b2, b3;
                ldm_x4t(b0, b1, b2, b3, sb + SV_ + krow * 512 + ((g ^ (krow & 7)) << 4));
                hmma(O[2 * nb],     a0, a1, a2, a3, b0, b1);
                hmma(O[2 * nb + 1], a0, a1, a2, a3, b2, b3);
            }
        }
    }

    // ---- li reduce (pair-local) ----
    li0 += __shfl_xor_sync(0xffffffffu, li0, 1);
    li0 += __shfl_xor_sync(0xffffffffu, li0, 2);
    li1 += __shfl_xor_sync(0xffffffffu, li1, 1);
    li1 += __shfl_xor_sync(0xffffffffu, li1, 2);
    int lrow = rg * 16 + (lane >> 2);
    liS[ch * 64 + lrow]     = li0;
    liS[ch * 64 + lrow + 8] = li1;
    PAIR_BAR(rg);
    float l0 = liS[lrow] + liS[64 + lrow];
    float l1 = liS[lrow + 8] + liS[64 + lrow + 8];

    if (!split) {
        float inv0 = 1.0f / l0, inv1 = 1.0f / l1;
        float* dst0 = out + (((size_t)(bb * S_ + q0 + lrow)) << 8);
        float* dst1 = dst0 + (8 << 8);
        #pragma unroll
        for (int j = 0; j < 16; j++) {
            int col = ch * 128 + j * 8 + (lane & 3) * 2;
            *(float2*)(dst0 + col) = make_float2(O[j][0] * inv0, O[j][1] * inv0);
            *(float2*)(dst1 + col) = make_float2(O[j][2] * inv1, O[j][3] * inv1);
        }
    } else {
        int base = ((qt - 16) * 8 + bb) * 2 + chunk;
        float* dst0 = g_pO + (size_t)base * 16384 + lrow * 256;
        float* dst1 = dst0 + 8 * 256;
        #pragma unroll
        for (int j = 0; j < 16; j++) {
            int col = ch * 128 + j * 8 + (lane & 3) * 2;
            *(float2*)(dst0 + col) = make_float2(O[j][0], O[j][1]);
            *(float2*)(dst1 + col) = make_float2(O[j][2], O[j][3]);
        }
        if (ch == 0 && (lane & 3) == 0) {
            g_pLi[base * 64 + lrow]     = l0;
            g_pLi[base * 64 + lrow + 8] = l1;
        }
    }
}

// ----------------------------- merge (split-K combine) ---------------------
__global__ __launch_bounds__(256) void merge_kernel(float* __restrict__ out) {
    const int t = blockIdx.x;            // 0..127: (qt-16)*8 + b
    const int qt = 16 + (t >> 3), bb = t & 7;
    const int tid = threadIdx.x;
    const float* O0 = g_pO + (size_t)(t * 2) * 16384;
    const float* O1 = O0 + 16384;
    const float* l0 = g_pLi + t * 2 * 64;
    const float* l1 = l0 + 64;

    int r = tid >> 2, cq = (tid & 3) * 64;
    float inv = 1.0f / (l0[r] + l1[r]);
    const float4* a4 = (const float4*)(O0 + r * 256 + cq);
    const float4* b4 = (const float4*)(O1 + r * 256 + cq);
    float4* o4 = (float4*)(out + (((size_t)(bb * S_ + qt * 64 + r)) << 8) + cq);
    #pragma unroll
    for (int i = 0; i < 16; i++) {
        float4 x = a4[i], y = b4[i];
        o4[i] = make_float4((x.x + y.x) * inv, (x.y + y.y) * inv,
                            (x.z + y.z) * inv, (x.w + y.w) * inv);
    }
}

// ---------------------------------------------------------------------------
extern "C" void kernel_launch(void* const* d_in, const int* in_sizes, int n_in,
                              void* d_out, int out_size) {
    const float* x  = (const float*)d_in[0];
    const float* wq = (const float*)d_in[1];
    const float* wk = (const float*)d_in[2];
    const float* wv = (const float*)d_in[3];
    float* out = (float*)d_out;

    cudaFuncSetAttribute(proj_kernel,  cudaFuncAttributeMaxDynamicSharedMemorySize, PRJ_SMEM);
    cudaFuncSetAttribute(flash_kernel, cudaFuncAttributeMaxDynamicSharedMemorySize, FL_SMEM);

    prep_kernel<<<4416, 256>>>(x, wq, wk, wv);
    proj_kernel<<<dim3(64, 2), 512, PRJ_SMEM>>>();
    flash_kernel<<<384, 256, FL_SMEM>>>(out);
    merge_kernel<<<128, 256>>>(out);
}

// round 13
// speedup vs baseline: 1.6929x; 1.6929x over previous
#include <cuda_runtime.h>
#include <cuda_fp16.h>
#include <cstdint>
#include <math.h>

#define B_ 8
#define S_ 2048
#define H_ 256
#define BSROWS (B_*S_)

// ----------------------------- scratch ------------------------------------
__device__ __half g_xh[(size_t)BSROWS * H_];
__device__ __half g_qh[(size_t)BSROWS * H_];
__device__ __half g_kh[(size_t)BSROWS * H_];
__device__ __half g_vh[(size_t)BSROWS * H_];
__device__ __half g_wh[3 * H_ * H_];
__device__ float2 g_cs[S_ * (H_ / 2)];

// ----------------------------- PTX helpers --------------------------------
__device__ __forceinline__ uint32_t smem_u32(const void* p) {
    uint32_t a;
    asm("{ .reg .u64 t; cvta.to.shared.u64 t, %1; cvt.u32.u64 %0, t; }" : "=r"(a) : "l"(p));
    return a;
}
#define CP16(dst, src) asm volatile("cp.async.cg.shared.global [%0], [%1], 16;" :: "r"(dst), "l"(src))
#define CP_COMMIT()    asm volatile("cp.async.commit_group;" ::: "memory")
#define CP_WAIT(n)     asm volatile("cp.async.wait_group %0;" :: "n"(n) : "memory")
#define PAIR_BAR(id)   asm volatile("bar.sync %0, 64;" :: "r"((id) + 1) : "memory")

__device__ __forceinline__ void ldm_x4(uint32_t& r0, uint32_t& r1, uint32_t& r2,
                                       uint32_t& r3, uint32_t addr) {
    asm volatile("ldmatrix.sync.aligned.m8n8.x4.shared.b16 {%0,%1,%2,%3}, [%4];"
                 : "=r"(r0), "=r"(r1), "=r"(r2), "=r"(r3) : "r"(addr));
}
__device__ __forceinline__ void ldm_x4t(uint32_t& r0, uint32_t& r1, uint32_t& r2,
                                        uint32_t& r3, uint32_t addr) {
    asm volatile("ldmatrix.sync.aligned.m8n8.x4.trans.shared.b16 {%0,%1,%2,%3}, [%4];"
                 : "=r"(r0), "=r"(r1), "=r"(r2), "=r"(r3) : "r"(addr));
}
__device__ __forceinline__ void hmma(float* c, uint32_t a0, uint32_t a1, uint32_t a2,
                                     uint32_t a3, uint32_t b0, uint32_t b1) {
    asm volatile(
        "mma.sync.aligned.m16n8k16.row.col.f32.f16.f16.f32 "
        "{%0,%1,%2,%3}, {%4,%5,%6,%7}, {%8,%9}, {%0,%1,%2,%3};"
        : "+f"(c[0]), "+f"(c[1]), "+f"(c[2]), "+f"(c[3])
        : "r"(a0), "r"(a1), "r"(a2), "r"(a3), "r"(b0), "r"(b1));
}

// ----------------------------- prep (fused) --------------------------------
__global__ __launch_bounds__(256) void prep_kernel(
    const float* __restrict__ x, const float* __restrict__ wq,
    const float* __restrict__ wk, const float* __restrict__ wv)
{
    const int bid = blockIdx.x, tid = threadIdx.x;
    if (bid < 128) {
        int i = tid & 127;
        double e = -2.0 * ((double)i - 1.0) / 256.0;
        float theta = (float)exp(e * 9.210340371976184);   // ln(10000)
        int p0 = bid * 16 + (tid >> 7) * 8;
        #pragma unroll
        for (int p = 0; p < 8; p++) {
            int pos = p0 + p;
            float ang = __fmul_rn((float)pos, theta);
            float sv, cv;
            sincosf(ang, &sv, &cv);
            g_cs[pos * 128 + i] = make_float2(cv, sv);
        }
    } else if (bid < 320) {
        int zi = bid - 128;
        int z = zi >> 6;
        int i = (zi & 63) * 256 + tid;
        const float* w = (z == 0) ? wq : (z == 1) ? wk : wv;
        float4 v = ((const float4*)w)[i];
        __half2* dst = (__half2*)(g_wh + (size_t)z * H_ * H_);
        dst[2 * i]     = __floats2half2_rn(v.x, v.y);
        dst[2 * i + 1] = __floats2half2_rn(v.z, v.w);
    } else {
        int i = (bid - 320) * 256 + tid;
        float4 v = ((const float4*)x)[i];
        ((__half2*)g_xh)[2 * i]     = __floats2half2_rn(v.x, v.y);
        ((__half2*)g_xh)[2 * i + 1] = __floats2half2_rn(v.z, v.w);
    }
}

// ----------------------------- proj (HMMA, K-split pipelined) ---------------
// A-resident z-loop, CTA tile 256(M) x 128(N), K=256, one wave of 128 CTAs.
// B stored per z as two 32KB half-buffers; a 3rd spare half-buffer lets the
// NEXT z's first half prefetch during this z's compute, and the second half
// load hide under the next z's first compute phase.
#define PRJ_SMEM 229376
#define PA_  0u
#define PB0_ 131072u
#define PB1_ 163840u
#define PSP_ 196608u

__global__ __launch_bounds__(512, 1) void proj_kernel() {
    extern __shared__ char sm[];
    uint32_t sb = smem_u32(sm);
    const int tid = threadIdx.x, lane = tid & 31, w = tid >> 5;
    const int wm = w >> 1, wn = w & 1;
    const int m0 = blockIdx.x * 256, n0g = blockIdx.y * 128;

    const uint32_t H0base[3] = { PB0_, PSP_, PB1_ };
    const uint32_t H1base[3] = { PB1_, PB0_, PSP_ };

    // helper lambdas (inlined)
    auto loadBhalf = [&](int z, int halfk, uint32_t dst) {
        const __half* src = g_wh + (size_t)z * H_ * H_;
        for (int i = tid; i < 2048; i += 512) {
            int row = i >> 4, g = i & 15;
            uint32_t sw = row * 256 + ((g ^ (row & 7)) << 4);
            CP16(sb + dst + sw, src + (((size_t)(n0g + row)) << 8) + (halfk * 16 + g) * 8);
        }
    };

    // G1: A-half1 + B(z0) H0 ; G2: A-half2 + B(z0) H1
    for (int i = tid; i < 4096; i += 512) {
        int row = i >> 4, g = i & 15;
        uint32_t sw = row * 512 + ((g ^ (row & 7)) << 4);
        CP16(sb + PA_ + sw, g_xh + (((size_t)(m0 + row)) << 8) + g * 8);
    }
    loadBhalf(0, 0, H0base[0]);
    CP_COMMIT();
    for (int i = tid; i < 4096; i += 512) {
        int row = i >> 4, g = 16 + (i & 15);
        uint32_t sw = row * 512 + ((g ^ (row & 7)) << 4);
        CP16(sb + PA_ + sw, g_xh + (((size_t)(m0 + row)) << 8) + g * 8);
    }
    loadBhalf(0, 1, H1base[0]);
    CP_COMMIT();
    CP_WAIT(1);            // A-half1 + B(z0)H0 ready; invariant: 1 group pending
    __syncthreads();

    #pragma unroll 1
    for (int z = 0; z < 3; z++) {
        if (z < 2) { loadBhalf(z + 1, 0, H0base[z + 1]); CP_COMMIT(); }

        float O[2][8][4];
        #pragma unroll
        for (int mi = 0; mi < 2; mi++)
            #pragma unroll
            for (int j = 0; j < 8; j++)
                #pragma unroll
                for (int c = 0; c < 4; c++) O[mi][j][c] = 0.f;

        // ---- phase 1: ks 0..7 (A g<16, B from H0) ----
        #pragma unroll
        for (int ks = 0; ks < 8; ks++) {
            uint32_t A[2][4];
            #pragma unroll
            for (int mi = 0; mi < 2; mi++) {
                uint32_t aRow = wm * 32 + mi * 16 + (lane & 15);
                uint32_t g = ks * 2 + (lane >> 4);
                ldm_x4(A[mi][0], A[mi][1], A[mi][2], A[mi][3],
                       sb + PA_ + aRow * 512 + ((g ^ (aRow & 7)) << 4));
            }
            #pragma unroll
            for (int nb = 0; nb < 4; nb++) {
                uint32_t nrow = wn * 64 + nb * 16 + (lane & 7) + ((lane >> 4) << 3);
                uint32_t g = ks * 2 + ((lane >> 3) & 1);
                uint32_t b0, b1, b2, b3;
                ldm_x4(b0, b1, b2, b3,
                       sb + H0base[z] + nrow * 256 + ((g ^ (nrow & 7)) << 4));
                #pragma unroll
                for (int mi = 0; mi < 2; mi++) {
                    hmma(O[mi][2 * nb],     A[mi][0], A[mi][1], A[mi][2], A[mi][3], b0, b1);
                    hmma(O[mi][2 * nb + 1], A[mi][0], A[mi][1], A[mi][2], A[mi][3], b2, b3);
                }
            }
        }

        if (z < 2) CP_WAIT(1); else CP_WAIT(0);   // H1(z) landed
        __syncthreads();

        // ---- phase 2: ks 8..15 (A g>=16, B from H1) ----
        #pragma unroll
        for (int ks = 8; ks < 16; ks++) {
            uint32_t A[2][4];
            #pragma unroll
            for (int mi = 0; mi < 2; mi++) {
                uint32_t aRow = wm * 32 + mi * 16 + (lane & 15);
                uint32_t g = ks * 2 + (lane >> 4);
                ldm_x4(A[mi][0], A[mi][1], A[mi][2], A[mi][3],
                       sb + PA_ + aRow * 512 + ((g ^ (aRow & 7)) << 4));
            }
            #pragma unroll
            for (int nb = 0; nb < 4; nb++) {
                uint32_t nrow = wn * 64 + nb * 16 + (lane & 7) + ((lane >> 4) << 3);
                uint32_t g = (ks - 8) * 2 + ((lane >> 3) & 1);
                uint32_t b0, b1, b2, b3;
                ldm_x4(b0, b1, b2, b3,
                       sb + H1base[z] + nrow * 256 + ((g ^ (nrow & 7)) << 4));
                #pragma unroll
                for (int mi = 0; mi < 2; mi++) {
                    hmma(O[mi][2 * nb],     A[mi][0], A[mi][1], A[mi][2], A[mi][3], b0, b1);
                    hmma(O[mi][2 * nb + 1], A[mi][0], A[mi][1], A[mi][2], A[mi][3], b2, b3);
                }
            }
        }

        __syncthreads();                 // all B(z) reads done
        if (z < 2) { loadBhalf(z + 1, 1, H1base[z + 1]); CP_COMMIT(); }

        // ---- epilogue (overlaps H1(z+1) load) ----
        __half* outp = (z == 0) ? g_qh : (z == 1) ? g_kh : g_vh;
        #pragma unroll
        for (int mi = 0; mi < 2; mi++) {
            int r0 = m0 + wm * 32 + mi * 16 + (lane >> 2), r1 = r0 + 8;
            int pos0 = r0 & (S_ - 1), pos1 = r1 & (S_ - 1);
            #pragma unroll
            for (int j = 0; j < 8; j++) {
                int col = n0g + wn * 64 + j * 8 + (lane & 3) * 2;
                if (z < 2) {
                    float2 cs0 = g_cs[pos0 * 128 + (col >> 1)];
                    float2 cs1 = g_cs[pos1 * 128 + (col >> 1)];
                    *(__half2*)(outp + (((size_t)r0) << 8) + col) =
                        __floats2half2_rn(cs0.x * O[mi][j][0] + cs0.y * O[mi][j][1],
                                          -cs0.y * O[mi][j][0] + cs0.x * O[mi][j][1]);
                    *(__half2*)(outp + (((size_t)r1) << 8) + col) =
                        __floats2half2_rn(cs1.x * O[mi][j][2] + cs1.y * O[mi][j][3],
                                          -cs1.y * O[mi][j][2] + cs1.x * O[mi][j][3]);
                } else {
                    *(__half2*)(outp + (((size_t)r0) << 8) + col) =
                        __floats2half2_rn(O[mi][j][0], O[mi][j][1]);
                    *(__half2*)(outp + (((size_t)r1) << 8) + col) =
                        __floats2half2_rn(O[mi][j][2], O[mi][j][3]);
                }
            }
        }
        if (z < 2) {
            CP_WAIT(1);                  // H0(z+1) ready; H1(z+1) still pending
            __syncthreads();
        }
    }
}

// ----------------------------- flash (HMMA) --------------------------------
// Round-11 mainloop (known-good, at mma.sync roofline). Work decode now maps
// 18 groups x 8 batches = 144 CTAs: 4 singletons (qt 31..28) + 14 pairs
// (p, 27-p) of 29 iters -> max 32 iters (was 33), 144 SMs busy (was 128).
#define SQ_ 0
#define SK_ 32768
#define SV_ (32768*3)
#define SP_ (32768*5)
#define SLI_ (32768*5 + 9216)
#define FL_SMEM (32768*5 + 9216 + 512)
#define SCALE2 0.0901684400054f   /* log2(e)/16 */

__global__ __launch_bounds__(256, 1) void flash_kernel(float* __restrict__ out) {
    extern __shared__ char sm[];
    uint32_t sb = smem_u32(sm);
    float* liS = (float*)(sm + SLI_);
    const int tid = threadIdx.x, lane = tid & 31, w = tid >> 5;
    const int rg = w >> 1, ch = w & 1;
    const int b = blockIdx.y, g9 = blockIdx.x;

    int tiles[2], nt;
    if (g9 < 4) { tiles[0] = 31 - g9; tiles[1] = 0; nt = 1; }
    else        { tiles[0] = 27 - (g9 - 4); tiles[1] = g9 - 4; nt = 2; }

    for (int ti = 0; ti < nt; ti++) {
        const int qt = tiles[ti];
        const int q0 = qt * 64, nkt = qt + 1;
        __syncthreads();          // prior tile fully consumed

        for (int i = tid; i < 2048; i += 256) {
            int row = i >> 5, gg = i & 31;
            uint32_t sw = row * 512 + ((gg ^ (row & 7)) << 4);
            CP16(sb + SQ_ + sw, g_qh + (((size_t)(b * S_ + q0 + row)) << 8) + gg * 8);
            size_t go = (((size_t)(b * S_ + row)) << 8) + gg * 8;
            CP16(sb + SK_ + sw, g_kh + go);
            CP16(sb + SV_ + sw, g_vh + go);
        }
        CP_COMMIT();
        CP_WAIT(0);
        __syncthreads();

        uint32_t Qf[16][4];
        {
            const uint32_t aRow = rg * 16 + (lane & 15);
            const uint32_t aQbase = sb + SQ_ + aRow * 512;
            const int aSel = lane >> 4, aXor = aRow & 7;
            #pragma unroll
            for (int ks = 0; ks < 16; ks++)
                ldm_x4(Qf[ks][0], Qf[ks][1], Qf[ks][2], Qf[ks][3],
                       aQbase + (((ks * 2 + aSel) ^ aXor) << 4));
        }

        float O[16][4];
        #pragma unroll
        for (int j = 0; j < 16; j++)
            #pragma unroll
            for (int c = 0; c < 4; c++) O[j][c] = 0.f;
        float li0 = 0.f, li1 = 0.f;
        const int aSel = lane >> 4;

        for (int kt = 0; kt < nkt; kt++) {
            const int cur = kt & 1;
            if (kt > 0) {
                CP_WAIT(0);
                __syncthreads();
            }
            if (kt + 1 < nkt) {
                int nb = (kt + 1) & 1, k0n = (kt + 1) * 64;
                for (int i = tid; i < 2048; i += 256) {
                    int row = i >> 5, gg = i & 31;
                    uint32_t sw = row * 512 + ((gg ^ (row & 7)) << 4);
                    size_t go = (((size_t)(b * S_ + k0n + row)) << 8) + gg * 8;
                    CP16(sb + SK_ + nb * 32768 + sw, g_kh + go);
                    CP16(sb + SV_ + nb * 32768 + sw, g_vh + go);
                }
                CP_COMMIT();
            }

            // ---- QK^T ----
            float S4[4][4];
            #pragma unroll
            for (int j = 0; j < 4; j++)
                #pragma unroll
                for (int c = 0; c < 4; c++) S4[j][c] = 0.f;

            const uint32_t kBase = sb + SK_ + cur * 32768;
            #pragma unroll
            for (int ks = 0; ks < 16; ks++) {
                #pragma unroll
                for (int nblk = 0; nblk < 2; nblk++) {
                    uint32_t nrow = ch * 32 + nblk * 16 + (lane & 7) + ((lane >> 4) << 3);
                    uint32_t gg = ks * 2 + ((lane >> 3) & 1);
                    uint32_t b0, b1, b2, b3;
                    ldm_x4(b0, b1, b2, b3, kBase + nrow * 512 + ((gg ^ (nrow & 7)) << 4));
                    hmma(S4[2 * nblk],     Qf[ks][0], Qf[ks][1], Qf[ks][2], Qf[ks][3], b0, b1);
                    hmma(S4[2 * nblk + 1], Qf[ks][0], Qf[ks][1], Qf[ks][2], Qf[ks][3], b2, b3);
                }
            }

            // ---- softmax chunk ----
            {
                const int row0 = q0 + rg * 16 + (lane >> 2);
                const int colb = kt * 64 + ch * 32 + (lane & 3) * 2;
                const bool diag = (kt == qt);
                uint32_t pb = SP_ + (rg * 16 + (lane >> 2)) * 144 +
                              (ch * 32 + (lane & 3) * 2) * 2;
                #pragma unroll
                for (int cnk = 0; cnk < 4; cnk++) {
                    int c0 = colb + cnk * 8;
                    float p00 = exp2f(S4[cnk][0] * SCALE2);
                    float p01 = exp2f(S4[cnk][1] * SCALE2);
                    float p10 = exp2f(S4[cnk][2] * SCALE2);
                    float p11 = exp2f(S4[cnk][3] * SCALE2);
                    if (diag) {
                        if (c0     > row0) p00 = 0.f;
                        if (c0 + 1 > row0) p01 = 0.f;
                        if (c0     > row0 + 8) p10 = 0.f;
                        if (c0 + 1 > row0 + 8) p11 = 0.f;
                    }
                    li0 += p00 + p01;
                    li1 += p10 + p11;
                    *(__half2*)(sm + pb + cnk * 16)           = __floats2half2_rn(p00, p01);
                    *(__half2*)(sm + pb + cnk * 16 + 8 * 144) = __floats2half2_rn(p10, p11);
                }
            }
            PAIR_BAR(rg);

            // ---- PV ----
            const uint32_t vBase = sb + SV_ + cur * 32768;
            const uint32_t pBase = sb + SP_ + (rg * 16 + (lane & 15)) * 144;
            #pragma unroll
            for (int kc = 0; kc < 4; kc++) {
                uint32_t a0, a1, a2, a3;
                ldm_x4(a0, a1, a2, a3, pBase + ((kc * 2 + aSel) << 4));
                #pragma unroll
                for (int nb = 0; nb < 8; nb++) {
                    uint32_t n0v = ch * 128 + nb * 16;
                    uint32_t krow = kc * 16 + (lane & 7) + (((lane >> 3) & 1) << 3);
                    uint32_t gg = (n0v >> 3) + (lane >> 4);
                    uint32_t b0, b1, b2, b3;
                    ldm_x4t(b0, b1, b2, b3, vBase + krow * 512 + ((gg ^ (krow & 7)) << 4));
                    hmma(O[2 * nb],     a0, a1, a2, a3, b0, b1);
                    hmma(O[2 * nb + 1], a0, a1, a2, a3, b2, b3);
                }
            }
            PAIR_BAR(rg);
        }

        // ---- normalize + store ----
        li0 += __shfl_xor_sync(0xffffffffu, li0, 1);
        li0 += __shfl_xor_sync(0xffffffffu, li0, 2);
        li1 += __shfl_xor_sync(0xffffffffu, li1, 1);
        li1 += __shfl_xor_sync(0xffffffffu, li1, 2);
        int lrow = rg * 16 + (lane >> 2);
        liS[ch * 64 + lrow]     = li0;
        liS[ch * 64 + lrow + 8] = li1;
        PAIR_BAR(rg);
        float inv0 = 1.0f / (liS[lrow] + liS[64 + lrow]);
        float inv1 = 1.0f / (liS[lrow + 8] + liS[64 + lrow + 8]);

        float* dst0 = out + (((size_t)(b * S_ + q0 + lrow)) << 8);
        float* dst1 = dst0 + (8 << 8);
        #pragma unroll
        for (int j = 0; j < 16; j++) {
            int col = ch * 128 + j * 8 + (lane & 3) * 2;
            *(float2*)(dst0 + col) = make_float2(O[j][0] * inv0, O[j][1] * inv0);
            *(float2*)(dst1 + col) = make_float2(O[j][2] * inv1, O[j][3] * inv1);
        }
    }
}

// ---------------------------------------------------------------------------
extern "C" void kernel_launch(void* const* d_in, const int* in_sizes, int n_in,
                              void* d_out, int out_size) {
    const float* x  = (const float*)d_in[0];
    const float* wq = (const float*)d_in[1];
    const float* wk = (const float*)d_in[2];
    const float* wv = (const float*)d_in[3];
    float* out = (float*)d_out;

    cudaFuncSetAttribute(proj_kernel,  cudaFuncAttributeMaxDynamicSharedMemorySize, PRJ_SMEM);
    cudaFuncSetAttribute(flash_kernel, cudaFuncAttributeMaxDynamicSharedMemorySize, FL_SMEM);

    prep_kernel<<<4416, 256>>>(x, wq, wk, wv);
    proj_kernel<<<dim3(64, 2), 512, PRJ_SMEM>>>();
    flash_kernel<<<dim3(18, B_), 256, FL_SMEM>>>(out);
}

// round 14
// speedup vs baseline: 1.7547x; 1.0365x over previous
#include <cuda_runtime.h>
#include <cuda_fp16.h>
#include <cstdint>
#include <math.h>

#define B_ 8
#define S_ 2048
#define H_ 256
#define BSROWS (B_*S_)

// ----------------------------- scratch ------------------------------------
__device__ __half g_xh[(size_t)BSROWS * H_];
__device__ __half g_qh[(size_t)BSROWS * H_];
__device__ __half g_kh[(size_t)BSROWS * H_];
__device__ __half g_vh[(size_t)BSROWS * H_];
__device__ __half g_wh[3 * H_ * H_];
__device__ float2 g_cs[S_ * (H_ / 2)];

// ----------------------------- PTX helpers --------------------------------
__device__ __forceinline__ uint32_t smem_u32(const void* p) {
    uint32_t a;
    asm("{ .reg .u64 t; cvta.to.shared.u64 t, %1; cvt.u32.u64 %0, t; }" : "=r"(a) : "l"(p));
    return a;
}
#define CP16(dst, src) asm volatile("cp.async.cg.shared.global [%0], [%1], 16;" :: "r"(dst), "l"(src))
#define CP_COMMIT()    asm volatile("cp.async.commit_group;" ::: "memory")
#define CP_WAIT(n)     asm volatile("cp.async.wait_group %0;" :: "n"(n) : "memory")
#define PAIR_BAR(id)   asm volatile("bar.sync %0, 64;" :: "r"((id) + 1) : "memory")

__device__ __forceinline__ void ldm_x4(uint32_t& r0, uint32_t& r1, uint32_t& r2,
                                       uint32_t& r3, uint32_t addr) {
    asm volatile("ldmatrix.sync.aligned.m8n8.x4.shared.b16 {%0,%1,%2,%3}, [%4];"
                 : "=r"(r0), "=r"(r1), "=r"(r2), "=r"(r3) : "r"(addr));
}
__device__ __forceinline__ void ldm_x4t(uint32_t& r0, uint32_t& r1, uint32_t& r2,
                                        uint32_t& r3, uint32_t addr) {
    asm volatile("ldmatrix.sync.aligned.m8n8.x4.trans.shared.b16 {%0,%1,%2,%3}, [%4];"
                 : "=r"(r0), "=r"(r1), "=r"(r2), "=r"(r3) : "r"(addr));
}
__device__ __forceinline__ void hmma(float* c, uint32_t a0, uint32_t a1, uint32_t a2,
                                     uint32_t a3, uint32_t b0, uint32_t b1) {
    asm volatile(
        "mma.sync.aligned.m16n8k16.row.col.f32.f16.f16.f32 "
        "{%0,%1,%2,%3}, {%4,%5,%6,%7}, {%8,%9}, {%0,%1,%2,%3};"
        : "+f"(c[0]), "+f"(c[1]), "+f"(c[2]), "+f"(c[3])
        : "r"(a0), "r"(a1), "r"(a2), "r"(a3), "r"(b0), "r"(b1));
}

// ----------------------------- prep (fused) --------------------------------
__global__ __launch_bounds__(256) void prep_kernel(
    const float* __restrict__ x, const float* __restrict__ wq,
    const float* __restrict__ wk, const float* __restrict__ wv)
{
    const int bid = blockIdx.x, tid = threadIdx.x;
    if (bid < 128) {
        int i = tid & 127;
        double e = -2.0 * ((double)i - 1.0) / 256.0;
        float theta = (float)exp(e * 9.210340371976184);   // ln(10000)
        int p0 = bid * 16 + (tid >> 7) * 8;
        #pragma unroll
        for (int p = 0; p < 8; p++) {
            int pos = p0 + p;
            float ang = __fmul_rn((float)pos, theta);
            float sv, cv;
            sincosf(ang, &sv, &cv);
            g_cs[pos * 128 + i] = make_float2(cv, sv);
        }
    } else if (bid < 320) {
        int zi = bid - 128;
        int z = zi >> 6;
        int i = (zi & 63) * 256 + tid;
        const float* w = (z == 0) ? wq : (z == 1) ? wk : wv;
        float4 v = ((const float4*)w)[i];
        __half2* dst = (__half2*)(g_wh + (size_t)z * H_ * H_);
        dst[2 * i]     = __floats2half2_rn(v.x, v.y);
        dst[2 * i + 1] = __floats2half2_rn(v.z, v.w);
    } else {
        int i = (bid - 320) * 256 + tid;
        float4 v = ((const float4*)x)[i];
        ((__half2*)g_xh)[2 * i]     = __floats2half2_rn(v.x, v.y);
        ((__half2*)g_xh)[2 * i + 1] = __floats2half2_rn(v.z, v.w);
    }
}

// ----------------------------- proj (HMMA, 2 CTA/SM) ------------------------
// CTA tile 128(M) x 128(N), 256 thr (8 warps, warp tile 32x64). K streamed as
// 12 chunks (3 z x 4 kc of 64): A 16KB + B 16KB, double-buffered -> 64KB smem,
// 2 CTAs/SM, 256 CTAs all co-resident. Co-resident CTA hides load/epilogue.
// Per-output accumulation order identical to previous rounds (16 seq k-steps).
#define PRJ_SMEM 65536
__global__ __launch_bounds__(256, 2) void proj_kernel() {
    extern __shared__ char sm[];
    uint32_t sb = smem_u32(sm);
    const int tid = threadIdx.x, lane = tid & 31, w = tid >> 5;
    const int wm = w >> 1, wn = w & 1;
    const int m0 = blockIdx.x * 128, n0g = blockIdx.y * 128;

    // chunk buffers: buf b at b*32768; A at +0, B at +16384 (128 rows x 128B)
    auto load_chunk = [&](int t, int buf) {
        int z = t >> 2, kc = t & 3;
        const __half* wsrc = g_wh + (size_t)z * H_ * H_;
        uint32_t base = sb + buf * 32768;
        #pragma unroll
        for (int i = tid; i < 1024; i += 256) {
            int row = i >> 3, g = i & 7;
            uint32_t sw = row * 128 + ((g ^ (row & 7)) << 4);
            CP16(base + sw,
                 g_xh + (((size_t)(m0 + row)) << 8) + kc * 64 + g * 8);
            CP16(base + 16384 + sw,
                 wsrc + (((size_t)(n0g + row)) << 8) + kc * 64 + g * 8);
        }
    };

    load_chunk(0, 0);
    CP_COMMIT();

    float O[2][8][4];
    #pragma unroll
    for (int mi = 0; mi < 2; mi++)
        #pragma unroll
        for (int j = 0; j < 8; j++)
            #pragma unroll
            for (int c = 0; c < 4; c++) O[mi][j][c] = 0.f;

    #pragma unroll 1
    for (int t = 0; t < 12; t++) {
        const int cur = t & 1;
        if (t + 1 < 12) { load_chunk(t + 1, cur ^ 1); CP_COMMIT(); }
        if (t + 1 < 12) CP_WAIT(1); else CP_WAIT(0);
        __syncthreads();                        // chunk t visible

        const uint32_t aBase = sb + cur * 32768;
        const uint32_t bBase = aBase + 16384;
        #pragma unroll
        for (int ks = 0; ks < 4; ks++) {
            uint32_t A[2][4];
            #pragma unroll
            for (int mi = 0; mi < 2; mi++) {
                uint32_t aRow = wm * 32 + mi * 16 + (lane & 15);
                uint32_t g = ks * 2 + (lane >> 4);
                ldm_x4(A[mi][0], A[mi][1], A[mi][2], A[mi][3],
                       aBase + aRow * 128 + ((g ^ (aRow & 7)) << 4));
            }
            #pragma unroll
            for (int nb = 0; nb < 4; nb++) {
                uint32_t nrow = wn * 64 + nb * 16 + (lane & 7) + ((lane >> 4) << 3);
                uint32_t g = ks * 2 + ((lane >> 3) & 1);
                uint32_t b0, b1, b2, b3;
                ldm_x4(b0, b1, b2, b3, bBase + nrow * 128 + ((g ^ (nrow & 7)) << 4));
                #pragma unroll
                for (int mi = 0; mi < 2; mi++) {
                    hmma(O[mi][2 * nb],     A[mi][0], A[mi][1], A[mi][2], A[mi][3], b0, b1);
                    hmma(O[mi][2 * nb + 1], A[mi][0], A[mi][1], A[mi][2], A[mi][3], b2, b3);
                }
            }
        }

        // z boundary: epilogue (RoPE for z<2), then reset accumulators
        if ((t & 3) == 3) {
            const int z = t >> 2;
            __half* outp = (z == 0) ? g_qh : (z == 1) ? g_kh : g_vh;
            #pragma unroll
            for (int mi = 0; mi < 2; mi++) {
                int r0 = m0 + wm * 32 + mi * 16 + (lane >> 2), r1 = r0 + 8;
                int pos0 = r0 & (S_ - 1), pos1 = r1 & (S_ - 1);
                #pragma unroll
                for (int j = 0; j < 8; j++) {
                    int col = n0g + wn * 64 + j * 8 + (lane & 3) * 2;
                    if (z < 2) {
                        float2 cs0 = g_cs[pos0 * 128 + (col >> 1)];
                        float2 cs1 = g_cs[pos1 * 128 + (col >> 1)];
                        *(__half2*)(outp + (((size_t)r0) << 8) + col) =
                            __floats2half2_rn(cs0.x * O[mi][j][0] + cs0.y * O[mi][j][1],
                                              -cs0.y * O[mi][j][0] + cs0.x * O[mi][j][1]);
                        *(__half2*)(outp + (((size_t)r1) << 8) + col) =
                            __floats2half2_rn(cs1.x * O[mi][j][2] + cs1.y * O[mi][j][3],
                                              -cs1.y * O[mi][j][2] + cs1.x * O[mi][j][3]);
                    } else {
                        *(__half2*)(outp + (((size_t)r0) << 8) + col) =
                            __floats2half2_rn(O[mi][j][0], O[mi][j][1]);
                        *(__half2*)(outp + (((size_t)r1) << 8) + col) =
                            __floats2half2_rn(O[mi][j][2], O[mi][j][3]);
                    }
                    #pragma unroll
                    for (int c = 0; c < 4; c++) O[mi][j][c] = 0.f;
                }
            }
        }
        __syncthreads();                        // buf cur free for t+2's load
    }
}

// ----------------------------- flash (HMMA) --------------------------------
// Round-13 (at mma.sync roofline): 18 groups x 8 batches = 144 CTAs,
// 4 singletons (qt 31..28) + 14 pairs (p, 27-p), max 32 iters.
#define SQ_ 0
#define SK_ 32768
#define SV_ (32768*3)
#define SP_ (32768*5)
#define SLI_ (32768*5 + 9216)
#define FL_SMEM (32768*5 + 9216 + 512)
#define SCALE2 0.0901684400054f   /* log2(e)/16 */

__global__ __launch_bounds__(256, 1) void flash_kernel(float* __restrict__ out) {
    extern __shared__ char sm[];
    uint32_t sb = smem_u32(sm);
    float* liS = (float*)(sm + SLI_);
    const int tid = threadIdx.x, lane = tid & 31, w = tid >> 5;
    const int rg = w >> 1, ch = w & 1;
    const int b = blockIdx.y, g9 = blockIdx.x;

    int tiles[2], nt;
    if (g9 < 4) { tiles[0] = 31 - g9; tiles[1] = 0; nt = 1; }
    else        { tiles[0] = 27 - (g9 - 4); tiles[1] = g9 - 4; nt = 2; }

    for (int ti = 0; ti < nt; ti++) {
        const int qt = tiles[ti];
        const int q0 = qt * 64, nkt = qt + 1;
        __syncthreads();

        for (int i = tid; i < 2048; i += 256) {
            int row = i >> 5, gg = i & 31;
            uint32_t sw = row * 512 + ((gg ^ (row & 7)) << 4);
            CP16(sb + SQ_ + sw, g_qh + (((size_t)(b * S_ + q0 + row)) << 8) + gg * 8);
            size_t go = (((size_t)(b * S_ + row)) << 8) + gg * 8;
            CP16(sb + SK_ + sw, g_kh + go);
            CP16(sb + SV_ + sw, g_vh + go);
        }
        CP_COMMIT();
        CP_WAIT(0);
        __syncthreads();

        uint32_t Qf[16][4];
        {
            const uint32_t aRow = rg * 16 + (lane & 15);
            const uint32_t aQbase = sb + SQ_ + aRow * 512;
            const int aSel = lane >> 4, aXor = aRow & 7;
            #pragma unroll
            for (int ks = 0; ks < 16; ks++)
                ldm_x4(Qf[ks][0], Qf[ks][1], Qf[ks][2], Qf[ks][3],
                       aQbase + (((ks * 2 + aSel) ^ aXor) << 4));
        }

        float O[16][4];
        #pragma unroll
        for (int j = 0; j < 16; j++)
            #pragma unroll
            for (int c = 0; c < 4; c++) O[j][c] = 0.f;
        float li0 = 0.f, li1 = 0.f;
        const int aSel = lane >> 4;

        for (int kt = 0; kt < nkt; kt++) {
            const int cur = kt & 1;
            if (kt > 0) {
                CP_WAIT(0);
                __syncthreads();
            }
            if (kt + 1 < nkt) {
                int nb = (kt + 1) & 1, k0n = (kt + 1) * 64;
                for (int i = tid; i < 2048; i += 256) {
                    int row = i >> 5, gg = i & 31;
                    uint32_t sw = row * 512 + ((gg ^ (row & 7)) << 4);
                    size_t go = (((size_t)(b * S_ + k0n + row)) << 8) + gg * 8;
                    CP16(sb + SK_ + nb * 32768 + sw, g_kh + go);
                    CP16(sb + SV_ + nb * 32768 + sw, g_vh + go);
                }
                CP_COMMIT();
            }

            // ---- QK^T ----
            float S4[4][4];
            #pragma unroll
            for (int j = 0; j < 4; j++)
                #pragma unroll
                for (int c = 0; c < 4; c++) S4[j][c] = 0.f;

            const uint32_t kBase = sb + SK_ + cur * 32768;
            #pragma unroll
            for (int ks = 0; ks < 16; ks++) {
                #pragma unroll
                for (int nblk = 0; nblk < 2; nblk++) {
                    uint32_t nrow = ch * 32 + nblk * 16 + (lane & 7) + ((lane >> 4) << 3);
                    uint32_t gg = ks * 2 + ((lane >> 3) & 1);
                    uint32_t b0, b1, b2, b3;
                    ldm_x4(b0, b1, b2, b3, kBase + nrow * 512 + ((gg ^ (nrow & 7)) << 4));
                    hmma(S4[2 * nblk],     Qf[ks][0], Qf[ks][1], Qf[ks][2], Qf[ks][3], b0, b1);
                    hmma(S4[2 * nblk + 1], Qf[ks][0], Qf[ks][1], Qf[ks][2], Qf[ks][3], b2, b3);
                }
            }

            // ---- softmax chunk ----
            {
                const int row0 = q0 + rg * 16 + (lane >> 2);
                const int colb = kt * 64 + ch * 32 + (lane & 3) * 2;
                const bool diag = (kt == qt);
                uint32_t pb = SP_ + (rg * 16 + (lane >> 2)) * 144 +
                              (ch * 32 + (lane & 3) * 2) * 2;
                #pragma unroll
                for (int cnk = 0; cnk < 4; cnk++) {
                    int c0 = colb + cnk * 8;
                    float p00 = exp2f(S4[cnk][0] * SCALE2);
                    float p01 = exp2f(S4[cnk][1] * SCALE2);
                    float p10 = exp2f(S4[cnk][2] * SCALE2);
                    float p11 = exp2f(S4[cnk][3] * SCALE2);
                    if (diag) {
                        if (c0     > row0) p00 = 0.f;
                        if (c0 + 1 > row0) p01 = 0.f;
                        if (c0     > row0 + 8) p10 = 0.f;
                        if (c0 + 1 > row0 + 8) p11 = 0.f;
                    }
                    li0 += p00 + p01;
                    li1 += p10 + p11;
                    *(__half2*)(sm + pb + cnk * 16)           = __floats2half2_rn(p00, p01);
                    *(__half2*)(sm + pb + cnk * 16 + 8 * 144) = __floats2half2_rn(p10, p11);
                }
            }
            PAIR_BAR(rg);

            // ---- PV ----
            const uint32_t vBase = sb + SV_ + cur * 32768;
            const uint32_t pBase = sb + SP_ + (rg * 16 + (lane & 15)) * 144;
            #pragma unroll
            for (int kc = 0; kc < 4; kc++) {
                uint32_t a0, a1, a2, a3;
                ldm_x4(a0, a1, a2, a3, pBase + ((kc * 2 + aSel) << 4));
                #pragma unroll
                for (int nb = 0; nb < 8; nb++) {
                    uint32_t n0v = ch * 128 + nb * 16;
                    uint32_t krow = kc * 16 + (lane & 7) + (((lane >> 3) & 1) << 3);
                    uint32_t gg = (n0v >> 3) + (lane >> 4);
                    uint32_t b0, b1, b2, b3;
                    ldm_x4t(b0, b1, b2, b3, vBase + krow * 512 + ((gg ^ (krow & 7)) << 4));
                    hmma(O[2 * nb],     a0, a1, a2, a3, b0, b1);
                    hmma(O[2 * nb + 1], a0, a1, a2, a3, b2, b3);
                }
            }
            PAIR_BAR(rg);
        }

        // ---- normalize + store ----
        li0 += __shfl_xor_sync(0xffffffffu, li0, 1);
        li0 += __shfl_xor_sync(0xffffffffu, li0, 2);
        li1 += __shfl_xor_sync(0xffffffffu, li1, 1);
        li1 += __shfl_xor_sync(0xffffffffu, li1, 2);
        int lrow = rg * 16 + (lane >> 2);
        liS[ch * 64 + lrow]     = li0;
        liS[ch * 64 + lrow + 8] = li1;
        PAIR_BAR(rg);
        float inv0 = 1.0f / (liS[lrow] + liS[64 + lrow]);
        float inv1 = 1.0f / (liS[lrow + 8] + liS[64 + lrow + 8]);

        float* dst0 = out + (((size_t)(b * S_ + q0 + lrow)) << 8);
        float* dst1 = dst0 + (8 << 8);
        #pragma unroll
        for (int j = 0; j < 16; j++) {
            int col = ch * 128 + j * 8 + (lane & 3) * 2;
            *(float2*)(dst0 + col) = make_float2(O[j][0] * inv0, O[j][1] * inv0);
            *(float2*)(dst1 + col) = make_float2(O[j][2] * inv1, O[j][3] * inv1);
        }
    }
}

// ---------------------------------------------------------------------------
extern "C" void kernel_launch(void* const* d_in, const int* in_sizes, int n_in,
                              void* d_out, int out_size) {
    const float* x  = (const float*)d_in[0];
    const float* wq = (const float*)d_in[1];
    const float* wk = (const float*)d_in[2];
    const float* wv = (const float*)d_in[3];
    float* out = (float*)d_out;

    cudaFuncSetAttribute(proj_kernel,  cudaFuncAttributeMaxDynamicSharedMemorySize, PRJ_SMEM);
    cudaFuncSetAttribute(flash_kernel, cudaFuncAttributeMaxDynamicSharedMemorySize, FL_SMEM);

    prep_kernel<<<4416, 256>>>(x, wq, wk, wv);
    proj_kernel<<<dim3(128, 2), 256, PRJ_SMEM>>>();
    flash_kernel<<<dim3(18, B_), 256, FL_SMEM>>>(out);
}